// round 1
// baseline (speedup 1.0000x reference)
#include <cuda_runtime.h>
#include <math.h>

#ifndef M_PI
#define M_PI 3.14159265358979323846
#endif

#define NLAT 256
#define NLON 256
#define LMAX 128
#define MMAX 129
#define CIN 32
#define COUT 32
#define BATCH 8
#define NPLANE 258            // 2*MMAX (re/im interleaved planes)
#define BC (BATCH*CIN)        // 256
#define NCOEF (2*LMAX*MMAX)   // 33024
#define ROWS_BCK (BC*NLAT)    // 65536

// ---------------- device scratch (static, zero-init .bss) ----------------
__device__ float g_w[NLAT];
__device__ float g_seed[MMAX];
__device__ float g_ab[MMAX*LMAX*2];
__device__ float g_PCT[MMAX*LMAX*NLAT];     // [m][l][k]
__device__ float g_PCTW[MMAX*LMAX*NLAT];    // [m][l][k] * w[k]
__device__ float g_F[NLON*NPLANE];          // forward DFT matrix [n][2m+r]
__device__ float g_G[NPLANE*NLON];          // inverse DFT matrix [2m+r][n]
__device__ float g_XH[(size_t)NPLANE*ROWS_BCK];   // [2m+r][bc*256+k]
__device__ float g_SPT[(size_t)NPLANE*BC*LMAX];   // [2m+r][bc][l]
__device__ float g_SP [(size_t)BC*LMAX*NPLANE];   // [bc][l][2m+r] == [bc][x]
__device__ float g_OUT[(size_t)BC*NCOEF];         // [bo][x]
__device__ float g_OUTT[(size_t)NPLANE*BC*LMAX];  // [2m+r][bo][l]
__device__ float g_RR[(size_t)NPLANE*ROWS_BCK];   // [2m+r][bo*256+k]

// ---------------- table builders ----------------

// Clenshaw-Curtis weights (double precision; 256 threads, 1 block)
__global__ void tab_weights() {
    int j = threadIdx.x;
    double tj = M_PI * (double)j / (double)(NLAT - 1);
    double S = 0.0;
    for (int k = 1; k <= (NLAT - 1) / 2; k++)
        S += cos(2.0 * tj * (double)k) * (2.0 / (4.0 * (double)k * k - 1.0));
    double c = (j == 0 || j == NLAT - 1) ? 1.0 : 2.0;
    g_w[j] = (float)(c / (double)(NLAT - 1) * (1.0 - S));
}

// Recurrence coefficients a(l,m), b(l,m) and diagonal seeds
__global__ void tab_ab() {
    int t = blockIdx.x * blockDim.x + threadIdx.x;
    if (t >= MMAX * LMAX) return;
    int m = t / LMAX, l = t % LMAX;
    if (l == 0)
        g_seed[m] = (m >= 1) ? (float)sqrt((2.0 * m + 1.0) / (2.0 * m)) : 0.f;
    float a = 0.f, b = 0.f;
    if (l >= m + 2) {
        double ld = l, md = m;
        a = (float)sqrt((4.0 * ld * ld - 1.0) / (ld * ld - md * md));
        b = (float)sqrt(((ld - 1.0) * (ld - 1.0) - md * md) /
                        (4.0 * (ld - 1.0) * (ld - 1.0) - 1.0));
    }
    g_ab[t * 2] = a;
    g_ab[t * 2 + 1] = b;
}

// Associated Legendre tables: one thread per (m,k), upward recurrence in l
__global__ void tab_leg() {
    int t = blockIdx.x * blockDim.x + threadIdx.x;
    if (t >= MMAX * NLAT) return;
    int m = t / NLAT, k = t % NLAT;
    double td = M_PI * (double)k / (double)(NLAT - 1);
    float ct = (float)cos(td), st = (float)sin(td);
    float w = g_w[k];
    float pmm = 0.28209479177387814f;  // 1/sqrt(4*pi)
    for (int mm = 1; mm <= m; mm++) pmm *= -g_seed[mm] * st;

    int idx = (m * LMAX) * NLAT + k;
    for (int l = 0; l < m && l < LMAX; l++) { g_PCT[idx] = 0.f; g_PCTW[idx] = 0.f; idx += NLAT; }
    if (m < LMAX) {
        float pm2 = pmm;
        g_PCT[idx] = pm2; g_PCTW[idx] = pm2 * w; idx += NLAT;
        if (m + 1 < LMAX) {
            float pm1 = sqrtf(2.f * m + 3.f) * ct * pm2;
            g_PCT[idx] = pm1; g_PCTW[idx] = pm1 * w; idx += NLAT;
            for (int l = m + 2; l < LMAX; l++) {
                float a = g_ab[(m * LMAX + l) * 2];
                float b = g_ab[(m * LMAX + l) * 2 + 1];
                float pn = a * (ct * pm1 - b * pm2);
                g_PCT[idx] = pn; g_PCTW[idx] = pn * w; idx += NLAT;
                pm2 = pm1; pm1 = pn;
            }
        }
    }
}

// Forward DFT matrix: F[n][2m+r] = (2pi/256) * {cos, -sin}(2*pi*m*n/256)
__global__ void tab_F() {
    int t = blockIdx.x * blockDim.x + threadIdx.x;
    if (t >= NLON * NPLANE) return;
    int n = t / NPLANE, col = t % NPLANE;
    int m = col >> 1, r = col & 1;
    double ang = 2.0 * M_PI * (double)(m * n) / (double)NLON;
    double s = 2.0 * M_PI / (double)NLON;
    g_F[t] = (float)(r == 0 ? s * cos(ang) : -s * sin(ang));
}

// Inverse DFT matrix: G[2m+r][n] = c_m * {cos, -sin}(2*pi*m*n/256), c_0=c_128=1 else 2
__global__ void tab_G() {
    int t = blockIdx.x * blockDim.x + threadIdx.x;
    if (t >= NPLANE * NLON) return;
    int p = t / NLON, n = t % NLON;
    int m = p >> 1, r = p & 1;
    double c = (m == 0 || m == MMAX - 1) ? 1.0 : 2.0;
    double ang = 2.0 * M_PI * (double)(m * n) / (double)NLON;
    g_G[t] = (float)(r == 0 ? c * cos(ang) : -c * sin(ang));
}

// ---------------- generic tiled SGEMM ----------------
// C[M,N] = A * B, contraction over K.
//  TA=false: A[m][k] (lda over m)     TA=true: A[k][m] (lda over k)
//  TB=false: B[k][n]                  TB=true:  B[n][k]
//  TC=false: C[m][n] (ldc over m)     TC=true:  C[n][m] (ldc over n)
//  BHALF: batch z advances B by (z>>1)*sB (re/im share the Legendre plane)
template<int BM, int BN, int BK, bool TA, bool TB, bool TC, bool BHALF>
__global__ void __launch_bounds__(256) sgemm_k(
    const float* __restrict__ A, const float* __restrict__ B, float* __restrict__ C,
    int M, int N, int K, int lda, int ldb, int ldc,
    int sA, int sB, int sC)
{
    __shared__ float As[BK][BM];
    __shared__ float Bs[BK][BN];
    int z = blockIdx.z;
    A += (size_t)z * sA;
    B += (size_t)(BHALF ? (z >> 1) : z) * sB;
    C += (size_t)z * sC;
    int bm = blockIdx.x * BM, bn = blockIdx.y * BN;
    int tid = threadIdx.x;
    int tm = (tid & 15) * 4, tn = (tid >> 4) * 4;
    float acc[4][4] = {};

    for (int k0 = 0; k0 < K; k0 += BK) {
        #pragma unroll
        for (int j = 0; j < (BM * BK / 1024); j++) { }  // (compile-time no-op)
        #pragma unroll
        for (int j = 0; j < 4; j++) {
            int id = tid * 4 + j;
            int m, kk;
            if (TA) { m = id % BM; kk = id / BM; }
            else    { kk = id % BK; m = id / BK; }
            int gm = bm + m, gk = k0 + kk;
            float v = 0.f;
            if (gm < M && gk < K)
                v = TA ? A[(size_t)gk * lda + gm] : A[(size_t)gm * lda + gk];
            As[kk][m] = v;
        }
        #pragma unroll
        for (int j = 0; j < 4; j++) {
            int id = tid * 4 + j;
            int n, kk;
            if (TB) { kk = id % BK; n = id / BK; }
            else    { n = id % BN; kk = id / BN; }
            int gn = bn + n, gk = k0 + kk;
            float v = 0.f;
            if (gn < N && gk < K)
                v = TB ? B[(size_t)gn * ldb + gk] : B[(size_t)gk * ldb + gn];
            Bs[kk][n] = v;
        }
        __syncthreads();
        #pragma unroll
        for (int kk = 0; kk < BK; kk++) {
            float4 av = *reinterpret_cast<const float4*>(&As[kk][tm]);
            float4 bv = *reinterpret_cast<const float4*>(&Bs[kk][tn]);
            float a[4] = {av.x, av.y, av.z, av.w};
            float b[4] = {bv.x, bv.y, bv.z, bv.w};
            #pragma unroll
            for (int i = 0; i < 4; i++)
                #pragma unroll
                for (int jj = 0; jj < 4; jj++)
                    acc[i][jj] += a[i] * b[jj];
        }
        __syncthreads();
    }

    #pragma unroll
    for (int i = 0; i < 4; i++) {
        int gm = bm + tm + i;
        if (gm >= M) continue;
        #pragma unroll
        for (int jj = 0; jj < 4; jj++) {
            int gn = bn + tn + jj;
            if (gn >= N) continue;
            if (TC) C[(size_t)gn * ldc + gm] = acc[i][jj];
            else    C[(size_t)gm * ldc + gn] = acc[i][jj];
        }
    }
}

// ---------------- tiled transpose: in[R][Cc] -> out[Cc][R] ----------------
__global__ void transpose_k(const float* __restrict__ in, float* __restrict__ out,
                            int R, int Cc) {
    __shared__ float t[32][33];
    int c0 = blockIdx.x * 32, r0 = blockIdx.y * 32;
    int tx = threadIdx.x;
    for (int j = threadIdx.y; j < 32; j += 8) {
        int r = r0 + j, c = c0 + tx;
        if (r < R && c < Cc) t[j][tx] = in[(size_t)r * Cc + c];
    }
    __syncthreads();
    for (int j = threadIdx.y; j < 32; j += 8) {
        int c = c0 + j, r = r0 + tx;
        if (c < Cc && r < R) out[(size_t)c * R + r] = t[tx][j];
    }
}

// ---------------- channel mix ----------------
// out[b*32+o][x] = sum_i spec[b*32+i][x] * w[(i*32+o)][x], 32 consecutive x per block
__global__ void __launch_bounds__(128) mix_k(const float* __restrict__ spec,
                                             const float* __restrict__ wgt,
                                             float* __restrict__ out) {
    __shared__ float s_sp[8][32][32];   // [b][i][x]   32 KB
    __shared__ float s_w[32][4][32];    // [i][ol][x]  16 KB
    int x0 = blockIdx.x * 32;
    int tx = threadIdx.x, ty = threadIdx.y;
    int tid = ty * 32 + tx;
    int warp = tid >> 5, wl = tid & 31;
    for (int row = warp; row < 256; row += 4)
        s_sp[row >> 5][row & 31][wl] = spec[row * NCOEF + x0 + wl];
    for (int oc = 0; oc < 8; oc++) {
        __syncthreads();
        for (int r = warp; r < 128; r += 4) {
            int i = r >> 2, ol = r & 3;
            s_w[i][ol][wl] = wgt[(i * COUT + oc * 4 + ol) * NCOEF + x0 + wl];
        }
        __syncthreads();
        float acc[8] = {};
        #pragma unroll
        for (int i = 0; i < 32; i++) {
            float wv = s_w[i][ty][tx];
            #pragma unroll
            for (int b = 0; b < 8; b++) acc[b] += s_sp[b][i][tx] * wv;
        }
        int o = oc * 4 + ty;
        #pragma unroll
        for (int b = 0; b < 8; b++)
            out[(b * COUT + o) * NCOEF + x0 + tx] = acc[b];
    }
}

// ---------------- launch ----------------
extern "C" void kernel_launch(void* const* d_in, const int* in_sizes, int n_in,
                              void* d_out, int out_size) {
    const float* x   = (const float*)d_in[0];   // [8,32,256,256]
    const float* wgt = (const float*)d_in[1];   // [32,32,33024]
    float* y = (float*)d_out;                   // [8,32,256,256]

    float *pPCT, *pPCTW, *pF, *pG, *pXH, *pSPT, *pSP, *pOUT, *pOUTT, *pRR;
    cudaGetSymbolAddress((void**)&pPCT,  g_PCT);
    cudaGetSymbolAddress((void**)&pPCTW, g_PCTW);
    cudaGetSymbolAddress((void**)&pF,    g_F);
    cudaGetSymbolAddress((void**)&pG,    g_G);
    cudaGetSymbolAddress((void**)&pXH,   g_XH);
    cudaGetSymbolAddress((void**)&pSPT,  g_SPT);
    cudaGetSymbolAddress((void**)&pSP,   g_SP);
    cudaGetSymbolAddress((void**)&pOUT,  g_OUT);
    cudaGetSymbolAddress((void**)&pOUTT, g_OUTT);
    cudaGetSymbolAddress((void**)&pRR,   g_RR);

    // tables (recomputed every launch; deterministic)
    tab_weights<<<1, 256>>>();
    tab_ab<<<(MMAX * LMAX + 255) / 256, 256>>>();
    tab_leg<<<(MMAX * NLAT + 255) / 256, 256>>>();
    tab_F<<<(NLON * NPLANE + 255) / 256, 256>>>();
    tab_G<<<(NPLANE * NLON + 255) / 256, 256>>>();

    // 1) forward DFT as GEMM, transposed write into plane-major XH
    sgemm_k<64, 64, 16, false, false, true, false>
        <<<dim3(ROWS_BCK / 64, (NPLANE + 63) / 64, 1), 256>>>(
            x, pF, pXH, ROWS_BCK, NPLANE, NLON, NLON, NPLANE, ROWS_BCK, 0, 0, 0);

    // 2) forward Legendre: batched over 258 planes (NT)
    sgemm_k<64, 64, 16, false, true, false, true>
        <<<dim3(BC / 64, LMAX / 64, NPLANE), 256>>>(
            pXH, pPCTW, pSPT, BC, LMAX, NLAT, NLAT, NLAT, LMAX,
            ROWS_BCK, LMAX * NLAT, BC * LMAX);

    // 3) transpose to coefficient order [bc][x]
    transpose_k<<<dim3((BC * LMAX) / 32, (NPLANE + 31) / 32), dim3(32, 8)>>>(
        pSPT, pSP, NPLANE, BC * LMAX);

    // 4) channel mix
    mix_k<<<NCOEF / 32, dim3(32, 4)>>>(pSP, wgt, pOUT);

    // 5) transpose back to plane-major [2m+r][bo][l]
    transpose_k<<<dim3((NPLANE + 31) / 32, (BC * LMAX) / 32), dim3(32, 8)>>>(
        pOUT, pOUTT, BC * LMAX, NPLANE);

    // 6) inverse Legendre: batched (NN)
    sgemm_k<64, 64, 16, false, false, false, true>
        <<<dim3(BC / 64, NLAT / 64, NPLANE), 256>>>(
            pOUTT, pPCT, pRR, BC, NLAT, LMAX, LMAX, NLAT, NLAT,
            BC * LMAX, LMAX * NLAT, ROWS_BCK);

    // 7) inverse DFT as GEMM (TN: A stored K-major)
    sgemm_k<64, 64, 16, true, false, false, false>
        <<<dim3(ROWS_BCK / 64, NLON / 64, 1), 256>>>(
            pRR, pG, y, ROWS_BCK, NLON, NPLANE, ROWS_BCK, NLON, NLON, 0, 0, 0);
}

// round 2
// speedup vs baseline: 1.1456x; 1.1456x over previous
#include <cuda_runtime.h>
#include <math.h>

#ifndef M_PI
#define M_PI 3.14159265358979323846
#endif

#define NLAT 256
#define NLON 256
#define LMAX 128
#define MMAX 129
#define CIN 32
#define COUT 32
#define BATCH 8
#define NPLANE 258            // 2*MMAX (re/im interleaved planes)
#define BC (BATCH*CIN)        // 256
#define NCOEF (2*LMAX*MMAX)   // 33024
#define ROWS_BCK (BC*NLAT)    // 65536

// ---------------- device scratch (static, zero-init .bss) ----------------
__device__ float g_w[NLAT];
__device__ float g_seed[MMAX];
__device__ float g_ab[MMAX*LMAX*2];
__device__ float g_PCT[MMAX*LMAX*NLAT];     // [m][l][k]
__device__ float g_PCTW[MMAX*LMAX*NLAT];    // [m][l][k] * w[k]
__device__ float g_F[NLON*NPLANE];          // forward DFT matrix [n][2m+r]
__device__ float g_G[NPLANE*NLON];          // inverse DFT matrix [2m+r][n]
__device__ float g_XH[(size_t)NPLANE*ROWS_BCK];   // [2m+r][bc*256+k]
__device__ float g_SPT[(size_t)NPLANE*BC*LMAX];   // [2m+r][bc][l]
__device__ float g_SP [(size_t)BC*LMAX*NPLANE];   // [bc][l][2m+r] == [bc][x]
__device__ float g_OUT[(size_t)BC*NCOEF];         // [bo][x]
__device__ float g_OUTT[(size_t)NPLANE*BC*LMAX];  // [2m+r][bo][l]
__device__ float g_RR[(size_t)NPLANE*ROWS_BCK];   // [2m+r][bo*256+k]

// ---------------- table builders ----------------

__global__ void tab_weights() {
    int j = threadIdx.x;
    double tj = M_PI * (double)j / (double)(NLAT - 1);
    double S = 0.0;
    for (int k = 1; k <= (NLAT - 1) / 2; k++)
        S += cos(2.0 * tj * (double)k) * (2.0 / (4.0 * (double)k * k - 1.0));
    double c = (j == 0 || j == NLAT - 1) ? 1.0 : 2.0;
    g_w[j] = (float)(c / (double)(NLAT - 1) * (1.0 - S));
}

__global__ void tab_ab() {
    int t = blockIdx.x * blockDim.x + threadIdx.x;
    if (t >= MMAX * LMAX) return;
    int m = t / LMAX, l = t % LMAX;
    if (l == 0)
        g_seed[m] = (m >= 1) ? (float)sqrt((2.0 * m + 1.0) / (2.0 * m)) : 0.f;
    float a = 0.f, b = 0.f;
    if (l >= m + 2) {
        double ld = l, md = m;
        a = (float)sqrt((4.0 * ld * ld - 1.0) / (ld * ld - md * md));
        b = (float)sqrt(((ld - 1.0) * (ld - 1.0) - md * md) /
                        (4.0 * (ld - 1.0) * (ld - 1.0) - 1.0));
    }
    g_ab[t * 2] = a;
    g_ab[t * 2 + 1] = b;
}

__global__ void tab_leg() {
    int t = blockIdx.x * blockDim.x + threadIdx.x;
    if (t >= MMAX * NLAT) return;
    int m = t / NLAT, k = t % NLAT;
    double td = M_PI * (double)k / (double)(NLAT - 1);
    float ct = (float)cos(td), st = (float)sin(td);
    float w = g_w[k];
    float pmm = 0.28209479177387814f;  // 1/sqrt(4*pi)
    for (int mm = 1; mm <= m; mm++) pmm *= -g_seed[mm] * st;

    int idx = (m * LMAX) * NLAT + k;
    for (int l = 0; l < m && l < LMAX; l++) { g_PCT[idx] = 0.f; g_PCTW[idx] = 0.f; idx += NLAT; }
    if (m < LMAX) {
        float pm2 = pmm;
        g_PCT[idx] = pm2; g_PCTW[idx] = pm2 * w; idx += NLAT;
        if (m + 1 < LMAX) {
            float pm1 = sqrtf(2.f * m + 3.f) * ct * pm2;
            g_PCT[idx] = pm1; g_PCTW[idx] = pm1 * w; idx += NLAT;
            for (int l = m + 2; l < LMAX; l++) {
                float a = g_ab[(m * LMAX + l) * 2];
                float b = g_ab[(m * LMAX + l) * 2 + 1];
                float pn = a * (ct * pm1 - b * pm2);
                g_PCT[idx] = pn; g_PCTW[idx] = pn * w; idx += NLAT;
                pm2 = pm1; pm1 = pn;
            }
        }
    }
}

__global__ void tab_F() {
    int t = blockIdx.x * blockDim.x + threadIdx.x;
    if (t >= NLON * NPLANE) return;
    int n = t / NPLANE, col = t % NPLANE;
    int m = col >> 1, r = col & 1;
    double ang = 2.0 * M_PI * (double)(m * n) / (double)NLON;
    double s = 2.0 * M_PI / (double)NLON;
    g_F[t] = (float)(r == 0 ? s * cos(ang) : -s * sin(ang));
}

__global__ void tab_G() {
    int t = blockIdx.x * blockDim.x + threadIdx.x;
    if (t >= NPLANE * NLON) return;
    int p = t / NLON, n = t % NLON;
    int m = p >> 1, r = p & 1;
    double c = (m == 0 || m == MMAX - 1) ? 1.0 : 2.0;
    double ang = 2.0 * M_PI * (double)(m * n) / (double)NLON;
    g_G[t] = (float)(r == 0 ? c * cos(ang) : -c * sin(ang));
}

// ---------------- SGEMM v2: 128x{128,64} tiles, 8x{8,4} micro ----------------
// C[M,N] = A * B, contraction over K.
//  TA=false: A[m][k]   TA=true: A[k][m]
//  TB=false: B[k][n]   TB=true: B[n][k]
//  TC=false: C[m][n]   TC=true: C[n][m]
//  BHALF: batch z advances B by (z>>1)*sB
// Thread layout: CG=BN/TN col groups; tx=tid%CG, ty=tid/CG.
// Rows (TM=8, split): {bm+ty*4+i, bm+BM/2+ty*4+i}.
// Cols: TN=8 split {bn+tx*4+j, bn+BN/2+tx*4+j}; TN=4 contiguous {bn+tx*4+j}.
template<int BM, int BN, int BK, int TN, bool TA, bool TB, bool TC, bool BHALF>
__global__ void __launch_bounds__((BM/8)*(BN/TN)) sgemm2(
    const float* __restrict__ A, const float* __restrict__ B, float* __restrict__ C,
    int M, int N, int K, int lda, int ldb, int ldc,
    int sA, int sB, int sC)
{
    constexpr int TM = 8;
    constexpr int THREADS = (BM / TM) * (BN / TN);
    constexpr int CG = BN / TN;
    __shared__ float As[BK][BM];
    __shared__ float Bs[BK][BN];

    int z = blockIdx.z;
    A += (size_t)z * sA;
    B += (size_t)(BHALF ? (z >> 1) : z) * sB;
    C += (size_t)z * sC;

    int bm = blockIdx.x * BM, bn = blockIdx.y * BN;
    int tid = threadIdx.x;
    int tx = tid % CG, ty = tid / CG;

    float acc[TM][TN] = {};

    for (int k0 = 0; k0 < K; k0 += BK) {
        // ---- load A tile (BM*BK elems, BM*BK/THREADS each) ----
        if (TA) {
            // A[k][m], contiguous in m: THREADS == BK*(BM/4)
            int kk = tid / (BM / 4);
            int m4 = (tid % (BM / 4)) * 4;
            int gk = k0 + kk;
            #pragma unroll
            for (int j = 0; j < 4; j++) {
                int gm = bm + m4 + j;
                As[kk][m4 + j] = (gm < M && gk < K) ? A[(size_t)gk * lda + gm] : 0.f;
            }
        } else {
            // A[m][k], contiguous in k: THREADS == BM*(BK/4)
            int m = tid / (BK / 4);
            int kq = (tid % (BK / 4)) * 4;
            int gm = bm + m;
            #pragma unroll
            for (int j = 0; j < 4; j++) {
                int gk = k0 + kq + j;
                As[kq + j][m] = (gm < M && gk < K) ? A[(size_t)gm * lda + gk] : 0.f;
            }
        }
        // ---- load B tile (BK*BN elems) ----
        constexpr int PERB = BK * BN / THREADS;
        if (TB) {
            // B[n][k], contiguous in k
            int n  = (tid * PERB) / BK;
            int kq = (tid * PERB) % BK;
            int gn = bn + n;
            #pragma unroll
            for (int e = 0; e < PERB; e++) {
                int gk = k0 + kq + e;
                Bs[kq + e][n] = (gn < N && gk < K) ? B[(size_t)gn * ldb + gk] : 0.f;
            }
        } else {
            // B[k][n], contiguous in n
            int kk = (tid * PERB) / BN;
            int nq = (tid * PERB) % BN;
            int gk = k0 + kk;
            #pragma unroll
            for (int e = 0; e < PERB; e++) {
                int gn = bn + nq + e;
                Bs[kk][nq + e] = (gn < N && gk < K) ? B[(size_t)gk * ldb + gn] : 0.f;
            }
        }
        __syncthreads();

        #pragma unroll
        for (int kk = 0; kk < BK; kk++) {
            float ra[TM], rb[TN];
            float4 a0 = *reinterpret_cast<const float4*>(&As[kk][ty * 4]);
            float4 a1 = *reinterpret_cast<const float4*>(&As[kk][BM / 2 + ty * 4]);
            ra[0] = a0.x; ra[1] = a0.y; ra[2] = a0.z; ra[3] = a0.w;
            ra[4] = a1.x; ra[5] = a1.y; ra[6] = a1.z; ra[7] = a1.w;
            float4 b0 = *reinterpret_cast<const float4*>(&Bs[kk][tx * 4]);
            rb[0] = b0.x; rb[1] = b0.y; rb[2] = b0.z; rb[3] = b0.w;
            if (TN == 8) {
                float4 b1 = *reinterpret_cast<const float4*>(&Bs[kk][BN / 2 + tx * 4]);
                rb[4] = b1.x; rb[5] = b1.y; rb[6] = b1.z; rb[7] = b1.w;
            }
            #pragma unroll
            for (int i = 0; i < TM; i++)
                #pragma unroll
                for (int j = 0; j < TN; j++)
                    acc[i][j] += ra[i] * rb[j];
        }
        __syncthreads();
    }

    // ---- epilogue ----
    #pragma unroll
    for (int i = 0; i < TM; i++) {
        int gm = bm + ((i < 4) ? (ty * 4 + i) : (BM / 2 + ty * 4 + i - 4));
        if (gm >= M) continue;
        #pragma unroll
        for (int j = 0; j < TN; j++) {
            int gn;
            if (TN == 8) gn = bn + ((j < 4) ? (tx * 4 + j) : (BN / 2 + tx * 4 + j - 4));
            else         gn = bn + tx * 4 + j;
            if (gn >= N) continue;
            if (TC) C[(size_t)gn * ldc + gm] = acc[i][j];
            else    C[(size_t)gm * ldc + gn] = acc[i][j];
        }
    }
}

// ---------------- tiled transpose: in[R][Cc] -> out[Cc][R] ----------------
__global__ void transpose_k(const float* __restrict__ in, float* __restrict__ out,
                            int R, int Cc) {
    __shared__ float t[32][33];
    int c0 = blockIdx.x * 32, r0 = blockIdx.y * 32;
    int tx = threadIdx.x;
    for (int j = threadIdx.y; j < 32; j += 8) {
        int r = r0 + j, c = c0 + tx;
        if (r < R && c < Cc) t[j][tx] = in[(size_t)r * Cc + c];
    }
    __syncthreads();
    for (int j = threadIdx.y; j < 32; j += 8) {
        int c = c0 + j, r = r0 + tx;
        if (c < Cc && r < R) out[(size_t)c * R + r] = t[tx][j];
    }
}

// ---------------- channel mix ----------------
__global__ void __launch_bounds__(128) mix_k(const float* __restrict__ spec,
                                             const float* __restrict__ wgt,
                                             float* __restrict__ out) {
    __shared__ float s_sp[8][32][32];   // [b][i][x]
    __shared__ float s_w[32][4][32];    // [i][ol][x]
    int x0 = blockIdx.x * 32;
    int tx = threadIdx.x, ty = threadIdx.y;
    int tid = ty * 32 + tx;
    int warp = tid >> 5, wl = tid & 31;
    for (int row = warp; row < 256; row += 4)
        s_sp[row >> 5][row & 31][wl] = spec[row * NCOEF + x0 + wl];
    for (int oc = 0; oc < 8; oc++) {
        __syncthreads();
        for (int r = warp; r < 128; r += 4) {
            int i = r >> 2, ol = r & 3;
            s_w[i][ol][wl] = wgt[(i * COUT + oc * 4 + ol) * NCOEF + x0 + wl];
        }
        __syncthreads();
        float acc[8] = {};
        #pragma unroll
        for (int i = 0; i < 32; i++) {
            float wv = s_w[i][ty][tx];
            #pragma unroll
            for (int b = 0; b < 8; b++) acc[b] += s_sp[b][i][tx] * wv;
        }
        int o = oc * 4 + ty;
        #pragma unroll
        for (int b = 0; b < 8; b++)
            out[(b * COUT + o) * NCOEF + x0 + tx] = acc[b];
    }
}

// ---------------- launch ----------------
extern "C" void kernel_launch(void* const* d_in, const int* in_sizes, int n_in,
                              void* d_out, int out_size) {
    const float* x   = (const float*)d_in[0];   // [8,32,256,256]
    const float* wgt = (const float*)d_in[1];   // [32,32,33024]
    float* y = (float*)d_out;                   // [8,32,256,256]

    float *pPCT, *pPCTW, *pF, *pG, *pXH, *pSPT, *pSP, *pOUT, *pOUTT, *pRR;
    cudaGetSymbolAddress((void**)&pPCT,  g_PCT);
    cudaGetSymbolAddress((void**)&pPCTW, g_PCTW);
    cudaGetSymbolAddress((void**)&pF,    g_F);
    cudaGetSymbolAddress((void**)&pG,    g_G);
    cudaGetSymbolAddress((void**)&pXH,   g_XH);
    cudaGetSymbolAddress((void**)&pSPT,  g_SPT);
    cudaGetSymbolAddress((void**)&pSP,   g_SP);
    cudaGetSymbolAddress((void**)&pOUT,  g_OUT);
    cudaGetSymbolAddress((void**)&pOUTT, g_OUTT);
    cudaGetSymbolAddress((void**)&pRR,   g_RR);

    // tables (recomputed every launch; deterministic)
    tab_weights<<<1, 256>>>();
    tab_ab<<<(MMAX * LMAX + 255) / 256, 256>>>();
    tab_leg<<<(MMAX * NLAT + 255) / 256, 256>>>();
    tab_F<<<(NLON * NPLANE + 255) / 256, 256>>>();
    tab_G<<<(NPLANE * NLON + 255) / 256, 256>>>();

    // 1) forward DFT as GEMM, transposed write into plane-major XH
    //    A=x[65536][256], B=F[256][258], C=XH[258][65536]
    sgemm2<128, 64, 8, 4, false, false, true, false>
        <<<dim3(ROWS_BCK / 128, (NPLANE + 63) / 64, 1), 256>>>(
            x, pF, pXH, ROWS_BCK, NPLANE, NLON, NLON, NPLANE, ROWS_BCK, 0, 0, 0);

    // 2) forward Legendre: batched over 258 planes (A=XH plane, B=PCTW^T)
    sgemm2<128, 128, 8, 8, false, true, false, true>
        <<<dim3(BC / 128, LMAX / 128, NPLANE), 256>>>(
            pXH, pPCTW, pSPT, BC, LMAX, NLAT, NLAT, NLAT, LMAX,
            ROWS_BCK, LMAX * NLAT, BC * LMAX);

    // 3) transpose to coefficient order [bc][x]
    transpose_k<<<dim3((BC * LMAX) / 32, (NPLANE + 31) / 32), dim3(32, 8)>>>(
        pSPT, pSP, NPLANE, BC * LMAX);

    // 4) channel mix
    mix_k<<<NCOEF / 32, dim3(32, 4)>>>(pSP, wgt, pOUT);

    // 5) transpose back to plane-major [2m+r][bo][l]
    transpose_k<<<dim3((NPLANE + 31) / 32, (BC * LMAX) / 32), dim3(32, 8)>>>(
        pOUT, pOUTT, BC * LMAX, NPLANE);

    // 6) inverse Legendre: batched (A=OUTT plane, B=PCT)
    sgemm2<128, 128, 8, 8, false, false, false, true>
        <<<dim3(BC / 128, NLAT / 128, NPLANE), 256>>>(
            pOUTT, pPCT, pRR, BC, NLAT, LMAX, LMAX, NLAT, NLAT,
            BC * LMAX, LMAX * NLAT, ROWS_BCK);

    // 7) inverse DFT as GEMM (A=RR stored plane-major -> TA=true)
    sgemm2<128, 128, 8, 8, true, false, false, false>
        <<<dim3(ROWS_BCK / 128, NLON / 128, 1), 256>>>(
            pRR, pG, y, ROWS_BCK, NLON, NPLANE, ROWS_BCK, NLON, NLON, 0, 0, 0);
}

// round 5
// speedup vs baseline: 1.6619x; 1.4508x over previous
#include <cuda_runtime.h>
#include <cuda_bf16.h>
#include <math.h>
#include <stdint.h>

#ifndef M_PI
#define M_PI 3.14159265358979323846
#endif

#define NLAT 256
#define NLON 256
#define LMAX 128
#define MMAX 129
#define CIN 32
#define COUT 32
#define BATCH 8
#define NPLANE 258            // 2*MMAX
#define GLD 260               // padded ld for Gt (float4 alignment)
#define BC (BATCH*CIN)        // 256
#define NCOEF (2*LMAX*MMAX)   // 33024
#define ROWS_BCK (BC*NLAT)    // 65536

// ---------------- device scratch ----------------
__device__ float g_w[NLAT];
__device__ float g_seed[MMAX];
__device__ float g_ab[MMAX*LMAX*2];
__device__ float g_PCTW [MMAX*LMAX*NLAT];   // [m][l][k]   (B for S2)
__device__ float g_PCT_T[MMAX*NLAT*LMAX];   // [m][k][l]   (B for S6)
__device__ float g_F[NPLANE*NLON];          // Ft[plane][n]  (B for S1)
__device__ float g_G[NLON*GLD];             // Gt[n][plane]  (B for S7), ld=260
__device__ float g_XH[(size_t)NPLANE*ROWS_BCK];   // [plane][bc*256+k]
__device__ float g_SPT[(size_t)NPLANE*BC*LMAX];   // [plane][bc][l]
__device__ float g_SP [(size_t)BC*LMAX*NPLANE];   // [bc][x]
__device__ float g_OUT[(size_t)BC*NCOEF];         // [bo][x]
__device__ float g_OUTT[(size_t)NPLANE*BC*LMAX];  // [plane][bo][l]
__device__ float g_RR[(size_t)NPLANE*ROWS_BCK];   // [plane][bo*256+k]

// ---------------- table builders ----------------
__global__ void tab_weights() {
    int j = threadIdx.x;
    double tj = M_PI * (double)j / (double)(NLAT - 1);
    double S = 0.0;
    for (int k = 1; k <= (NLAT - 1) / 2; k++)
        S += cos(2.0 * tj * (double)k) * (2.0 / (4.0 * (double)k * k - 1.0));
    double c = (j == 0 || j == NLAT - 1) ? 1.0 : 2.0;
    g_w[j] = (float)(c / (double)(NLAT - 1) * (1.0 - S));
}

__global__ void tab_ab() {
    int t = blockIdx.x * blockDim.x + threadIdx.x;
    if (t >= MMAX * LMAX) return;
    int m = t / LMAX, l = t % LMAX;
    if (l == 0)
        g_seed[m] = (m >= 1) ? (float)sqrt((2.0 * m + 1.0) / (2.0 * m)) : 0.f;
    float a = 0.f, b = 0.f;
    if (l >= m + 2) {
        double ld = l, md = m;
        a = (float)sqrt((4.0 * ld * ld - 1.0) / (ld * ld - md * md));
        b = (float)sqrt(((ld - 1.0) * (ld - 1.0) - md * md) /
                        (4.0 * (ld - 1.0) * (ld - 1.0) - 1.0));
    }
    g_ab[t * 2] = a;
    g_ab[t * 2 + 1] = b;
}

// writes PCTW[m][l][k] and PCT_T[m][k][l]
__global__ void tab_leg() {
    int t = blockIdx.x * blockDim.x + threadIdx.x;
    if (t >= MMAX * NLAT) return;
    int m = t / NLAT, k = t % NLAT;
    double td = M_PI * (double)k / (double)(NLAT - 1);
    float ct = (float)cos(td), st = (float)sin(td);
    float w = g_w[k];
    float pmm = 0.28209479177387814f;  // 1/sqrt(4*pi)
    for (int mm = 1; mm <= m; mm++) pmm *= -g_seed[mm] * st;

    float* pw = g_PCTW + (size_t)(m * LMAX) * NLAT + k;     // stride NLAT per l
    float* pt = g_PCT_T + ((size_t)m * NLAT + k) * LMAX;    // stride 1 per l
    for (int l = 0; l < m && l < LMAX; l++) { pw[0] = 0.f; pt[l] = 0.f; pw += NLAT; }
    if (m < LMAX) {
        float pm2 = pmm;
        pw[0] = pm2 * w; pt[m] = pm2; pw += NLAT;
        if (m + 1 < LMAX) {
            float pm1 = sqrtf(2.f * m + 3.f) * ct * pm2;
            pw[0] = pm1 * w; pt[m + 1] = pm1; pw += NLAT;
            for (int l = m + 2; l < LMAX; l++) {
                float a = g_ab[(m * LMAX + l) * 2];
                float b = g_ab[(m * LMAX + l) * 2 + 1];
                float pn = a * (ct * pm1 - b * pm2);
                pw[0] = pn * w; pt[l] = pn; pw += NLAT;
                pm2 = pm1; pm1 = pn;
            }
        }
    }
}

// Forward DFT matrix, plane-major: Ft[2m+r][n]
__global__ void tab_F() {
    int t = blockIdx.x * blockDim.x + threadIdx.x;
    if (t >= NPLANE * NLON) return;
    int p = t / NLON, n = t % NLON;
    int m = p >> 1, r = p & 1;
    double ang = 2.0 * M_PI * (double)((m * n) & (NLON - 1)) / (double)NLON;
    double s = 2.0 * M_PI / (double)NLON;
    g_F[t] = (float)(r == 0 ? s * cos(ang) : -s * sin(ang));
}

// Inverse DFT matrix, lon-major: Gt[n][2m+r], ld=260
__global__ void tab_G() {
    int t = blockIdx.x * blockDim.x + threadIdx.x;
    if (t >= NLON * NPLANE) return;
    int n = t / NPLANE, p = t % NPLANE;
    int m = p >> 1, r = p & 1;
    double c = (m == 0 || m == MMAX - 1) ? 1.0 : 2.0;
    double ang = 2.0 * M_PI * (double)((m * n) & (NLON - 1)) / (double)NLON;
    g_G[n * GLD + p] = (float)(r == 0 ? c * cos(ang) : -c * sin(ang));
}

// ---------------- mma.sync helpers ----------------
__device__ __forceinline__ uint32_t SWZ(uint32_t off) { return off ^ ((off >> 3) & 0x70); }

__device__ __forceinline__ uint32_t smem_u32(const void* p) {
    uint32_t a;
    asm("{ .reg .u64 t; cvta.to.shared.u64 t, %1; cvt.u32.u64 %0, t; }" : "=r"(a) : "l"(p));
    return a;
}
__device__ __forceinline__ void ldsm4(uint32_t* r, uint32_t addr) {
    asm volatile("ldmatrix.sync.aligned.m8n8.x4.shared.b16 {%0,%1,%2,%3}, [%4];"
        : "=r"(r[0]), "=r"(r[1]), "=r"(r[2]), "=r"(r[3]) : "r"(addr));
}
__device__ __forceinline__ void mma_bf16(float* c, const uint32_t* a, uint32_t b0, uint32_t b1) {
    asm volatile("mma.sync.aligned.m16n8k16.row.col.f32.bf16.bf16.f32 "
        "{%0,%1,%2,%3}, {%4,%5,%6,%7}, {%8,%9}, {%0,%1,%2,%3};"
        : "+f"(c[0]), "+f"(c[1]), "+f"(c[2]), "+f"(c[3])
        : "r"(a[0]), "r"(a[1]), "r"(a[2]), "r"(a[3]), "r"(b0), "r"(b1));
}
__device__ __forceinline__ void split2(float a, float b, uint32_t& hi, uint32_t& lo) {
    __nv_bfloat162 h = __floats2bfloat162_rn(a, b);
    hi = *reinterpret_cast<uint32_t*>(&h);
    __nv_bfloat162 l = __floats2bfloat162_rn(a - __bfloat162float(h.x),
                                             b - __bfloat162float(h.y));
    lo = *reinterpret_cast<uint32_t*>(&l);
}

// ---------------- unified tensor-core GEMM (mma.sync bf16, split-3) ----------------
// C[M,N] = A * B.  Block tile 128x128, K-chunk 64. 256 threads, 8 warps (2x4).
// A: ATRANS ? A[k*lda+m] : A[m*lda+k]    B: B[n*ldb+k] (rows n, K-major)
// C: CTRANS ? C[n*ldc+m] : C[m*ldc+n]
// D = Ahi*Bhi + Ahi*Blo + Alo*Bhi  (fp32 accumulate)
// smem: a_hi @0, a_lo @16K, b_hi @32K, b_lo @48K (each 128 rows x 128B, SW128)
#define MM_SMEM 65536
#define OFF_ALO 16384u
#define OFF_BHI 32768u
#define OFF_BLO 49152u

template<bool ATRANS, bool CTRANS, bool BHALF>
__global__ void __launch_bounds__(256, 2) mmagemm(
    const float* __restrict__ A, const float* __restrict__ B, float* __restrict__ C,
    int M, int N, int K, int lda, int ldb, int ldc, int sA, int sB, int sC)
{
    extern __shared__ char smem[];
    const uint32_t sbase = smem_u32(smem);
    const int tid = threadIdx.x;
    const int wid = tid >> 5;
    const int lane = tid & 31;

    int z = blockIdx.z;
    A += (size_t)z * sA;
    B += (size_t)(BHALF ? (z >> 1) : z) * sB;
    C += (size_t)z * sC;
    const int bm = blockIdx.x * 128;
    const int bn = blockIdx.y * 128;

    const int wm = wid & 1;   // m tile of 64
    const int wn = wid >> 1;  // n tile of 32

    float acc[4][4][4] = {};

    // lane-dependent ldmatrix base offsets (row = lane%16, 16B chunk = lane/16)
    const uint32_t aBase = (uint32_t)((wm * 64 + (lane & 15)) * 128 + ((lane >> 4) << 4));
    const uint32_t bBase = (uint32_t)((wn * 32 + (lane & 15)) * 128 + ((lane >> 4) << 4));

    const int NK = (K + 63) >> 6;
    for (int kt = 0; kt < NK; kt++) {
        const int k0 = kt << 6;

        // ---- load + convert A tile into smem ----
        if (!ATRANS) {
            int r = tid >> 1;
            int kh = (tid & 1) << 5;
            const float* p = A + (size_t)(bm + r) * lda + k0 + kh;
            #pragma unroll
            for (int q = 0; q < 8; q++) {
                int gk = k0 + kh + q * 4;
                float4 v;
                if (gk + 3 < K) v = *reinterpret_cast<const float4*>(p + q * 4);
                else {
                    v.x = (gk + 0 < K) ? p[q * 4 + 0] : 0.f;
                    v.y = (gk + 1 < K) ? p[q * 4 + 1] : 0.f;
                    v.z = (gk + 2 < K) ? p[q * 4 + 2] : 0.f;
                    v.w = (gk + 3 < K) ? p[q * 4 + 3] : 0.f;
                }
                uint32_t h0, l0, h1, l1;
                split2(v.x, v.y, h0, l0);
                split2(v.z, v.w, h1, l1);
                uint32_t off = SWZ((uint32_t)(r * 128 + (kh + q * 4) * 2));
                *reinterpret_cast<uint2*>(smem + off)           = make_uint2(h0, h1);
                *reinterpret_cast<uint2*>(smem + OFF_ALO + off) = make_uint2(l0, l1);
            }
        } else {
            int kr = tid >> 2;
            int mc = (tid & 3) << 5;
            int gk = k0 + kr;
            const float* p = A + (size_t)gk * lda + bm + mc;
            #pragma unroll
            for (int q = 0; q < 8; q++) {
                float4 v = make_float4(0.f, 0.f, 0.f, 0.f);
                if (gk < K) v = *reinterpret_cast<const float4*>(p + q * 4);
                float vv[4] = {v.x, v.y, v.z, v.w};
                #pragma unroll
                for (int j = 0; j < 4; j++) {
                    int m = mc + q * 4 + j;
                    __nv_bfloat16 h = __float2bfloat16(vv[j]);
                    __nv_bfloat16 lo = __float2bfloat16(vv[j] - __bfloat162float(h));
                    uint32_t off = SWZ((uint32_t)(m * 128 + kr * 2));
                    *reinterpret_cast<__nv_bfloat16*>(smem + off) = h;
                    *reinterpret_cast<__nv_bfloat16*>(smem + OFF_ALO + off) = lo;
                }
            }
        }
        // ---- load + convert B tile ----
        {
            int r = tid >> 1;
            int kh = (tid & 1) << 5;
            int gn = bn + r;
            const float* p = B + (size_t)gn * ldb + k0 + kh;
            bool nok = gn < N;
            #pragma unroll
            for (int q = 0; q < 8; q++) {
                int gk = k0 + kh + q * 4;
                float4 v = make_float4(0.f, 0.f, 0.f, 0.f);
                if (nok) {
                    if (gk + 3 < K) v = *reinterpret_cast<const float4*>(p + q * 4);
                    else {
                        if (gk + 0 < K) v.x = p[q * 4 + 0];
                        if (gk + 1 < K) v.y = p[q * 4 + 1];
                        if (gk + 2 < K) v.z = p[q * 4 + 2];
                        if (gk + 3 < K) v.w = p[q * 4 + 3];
                    }
                }
                uint32_t h0, l0, h1, l1;
                split2(v.x, v.y, h0, l0);
                split2(v.z, v.w, h1, l1);
                uint32_t off = SWZ((uint32_t)(r * 128 + (kh + q * 4) * 2));
                *reinterpret_cast<uint2*>(smem + OFF_BHI + off) = make_uint2(h0, h1);
                *reinterpret_cast<uint2*>(smem + OFF_BLO + off) = make_uint2(l0, l1);
            }
        }
        __syncthreads();

        // ---- MMA over 4 k-steps of 16 ----
        #pragma unroll
        for (int ks = 0; ks < 4; ks++) {
            uint32_t kb = (uint32_t)(ks * 32);   // kk*2 bytes

            uint32_t ah[4][4];
            #pragma unroll
            for (int mi = 0; mi < 4; mi++)
                ldsm4(ah[mi], sbase + SWZ(aBase + mi * 2048 + kb));

            uint32_t bh[4][2];
            #pragma unroll
            for (int g = 0; g < 2; g++) {
                uint32_t t[4];
                ldsm4(t, sbase + OFF_BHI + SWZ(bBase + g * 2048 + kb));
                bh[2 * g][0] = t[0]; bh[2 * g][1] = t[2];
                bh[2 * g + 1][0] = t[1]; bh[2 * g + 1][1] = t[3];
            }
            #pragma unroll
            for (int mi = 0; mi < 4; mi++)
                #pragma unroll
                for (int nb = 0; nb < 4; nb++)
                    mma_bf16(acc[mi][nb], ah[mi], bh[nb][0], bh[nb][1]);

            // Ahi * Blo
            #pragma unroll
            for (int g = 0; g < 2; g++) {
                uint32_t t[4];
                ldsm4(t, sbase + OFF_BLO + SWZ(bBase + g * 2048 + kb));
                #pragma unroll
                for (int mi = 0; mi < 4; mi++) {
                    mma_bf16(acc[mi][2 * g],     ah[mi], t[0], t[2]);
                    mma_bf16(acc[mi][2 * g + 1], ah[mi], t[1], t[3]);
                }
            }
            // Alo * Bhi
            #pragma unroll
            for (int mi = 0; mi < 4; mi++) {
                uint32_t al[4];
                ldsm4(al, sbase + OFF_ALO + SWZ(aBase + mi * 2048 + kb));
                #pragma unroll
                for (int nb = 0; nb < 4; nb++)
                    mma_bf16(acc[mi][nb], al, bh[nb][0], bh[nb][1]);
            }
        }
        __syncthreads();
    }

    // ---- epilogue ----
    #pragma unroll
    for (int mi = 0; mi < 4; mi++) {
        #pragma unroll
        for (int nb = 0; nb < 4; nb++) {
            int m0 = bm + wm * 64 + mi * 16 + (lane >> 2);
            int n0 = bn + wn * 32 + nb * 8 + ((lane & 3) << 1);
            float* a = acc[mi][nb];
            if (!CTRANS) {
                *reinterpret_cast<float2*>(&C[(size_t)m0 * ldc + n0]) =
                    make_float2(a[0], a[1]);
                *reinterpret_cast<float2*>(&C[(size_t)(m0 + 8) * ldc + n0]) =
                    make_float2(a[2], a[3]);
            } else {
                if (n0 < N) {
                    C[(size_t)n0 * ldc + m0]     = a[0];
                    C[(size_t)n0 * ldc + m0 + 8] = a[2];
                }
                if (n0 + 1 < N) {
                    C[(size_t)(n0 + 1) * ldc + m0]     = a[1];
                    C[(size_t)(n0 + 1) * ldc + m0 + 8] = a[3];
                }
            }
        }
    }
}

// ---------------- tiled transpose: in[R][Cc] -> out[Cc][R] ----------------
__global__ void transpose_k(const float* __restrict__ in, float* __restrict__ out,
                            int R, int Cc) {
    __shared__ float t[32][33];
    int c0 = blockIdx.x * 32, r0 = blockIdx.y * 32;
    int tx = threadIdx.x;
    for (int j = threadIdx.y; j < 32; j += 8) {
        int r = r0 + j, c = c0 + tx;
        if (r < R && c < Cc) t[j][tx] = in[(size_t)r * Cc + c];
    }
    __syncthreads();
    for (int j = threadIdx.y; j < 32; j += 8) {
        int c = c0 + j, r = r0 + tx;
        if (c < Cc && r < R) out[(size_t)c * R + r] = t[tx][j];
    }
}

// ---------------- channel mix ----------------
__global__ void __launch_bounds__(128) mix_k(const float* __restrict__ spec,
                                             const float* __restrict__ wgt,
                                             float* __restrict__ out) {
    __shared__ float s_sp[8][32][32];
    __shared__ float s_w[32][4][32];
    int x0 = blockIdx.x * 32;
    int tx = threadIdx.x, ty = threadIdx.y;
    int tid = ty * 32 + tx;
    int warp = tid >> 5, wl = tid & 31;
    for (int row = warp; row < 256; row += 4)
        s_sp[row >> 5][row & 31][wl] = spec[row * NCOEF + x0 + wl];
    for (int oc = 0; oc < 8; oc++) {
        __syncthreads();
        for (int r = warp; r < 128; r += 4) {
            int i = r >> 2, ol = r & 3;
            s_w[i][ol][wl] = wgt[(i * COUT + oc * 4 + ol) * NCOEF + x0 + wl];
        }
        __syncthreads();
        float acc[8] = {};
        #pragma unroll
        for (int i = 0; i < 32; i++) {
            float wv = s_w[i][ty][tx];
            #pragma unroll
            for (int b = 0; b < 8; b++) acc[b] += s_sp[b][i][tx] * wv;
        }
        int o = oc * 4 + ty;
        #pragma unroll
        for (int b = 0; b < 8; b++)
            out[(b * COUT + o) * NCOEF + x0 + tx] = acc[b];
    }
}

// ---------------- launch ----------------
extern "C" void kernel_launch(void* const* d_in, const int* in_sizes, int n_in,
                              void* d_out, int out_size) {
    const float* x   = (const float*)d_in[0];   // [8,32,256,256]
    const float* wgt = (const float*)d_in[1];   // [32,32,33024]
    float* y = (float*)d_out;                   // [8,32,256,256]

    float *pPCTW, *pPCT_T, *pF, *pG, *pXH, *pSPT, *pSP, *pOUT, *pOUTT, *pRR;
    cudaGetSymbolAddress((void**)&pPCTW,  g_PCTW);
    cudaGetSymbolAddress((void**)&pPCT_T, g_PCT_T);
    cudaGetSymbolAddress((void**)&pF,     g_F);
    cudaGetSymbolAddress((void**)&pG,     g_G);
    cudaGetSymbolAddress((void**)&pXH,    g_XH);
    cudaGetSymbolAddress((void**)&pSPT,   g_SPT);
    cudaGetSymbolAddress((void**)&pSP,    g_SP);
    cudaGetSymbolAddress((void**)&pOUT,   g_OUT);
    cudaGetSymbolAddress((void**)&pOUTT,  g_OUTT);
    cudaGetSymbolAddress((void**)&pRR,    g_RR);

    cudaFuncSetAttribute(mmagemm<false, true,  false>,
                         cudaFuncAttributeMaxDynamicSharedMemorySize, MM_SMEM);
    cudaFuncSetAttribute(mmagemm<false, false, true>,
                         cudaFuncAttributeMaxDynamicSharedMemorySize, MM_SMEM);
    cudaFuncSetAttribute(mmagemm<true,  false, false>,
                         cudaFuncAttributeMaxDynamicSharedMemorySize, MM_SMEM);

    // tables
    tab_weights<<<1, 256>>>();
    tab_ab<<<(MMAX * LMAX + 255) / 256, 256>>>();
    tab_leg<<<(MMAX * NLAT + 255) / 256, 256>>>();
    tab_F<<<(NPLANE * NLON + 255) / 256, 256>>>();
    tab_G<<<(NLON * NPLANE + 255) / 256, 256>>>();

    // 1) forward DFT: A=x[65536][256], B=Ft[258][256], C=XH[plane][65536] (CTRANS)
    mmagemm<false, true, false>
        <<<dim3(ROWS_BCK / 128, 3, 1), 256, MM_SMEM>>>(
            x, pF, pXH, ROWS_BCK, NPLANE, NLON, NLON, NLON, ROWS_BCK, 0, 0, 0);

    // 2) forward Legendre: per plane, A=XH[plane](256x256), B=PCTW[m](128x256)
    mmagemm<false, false, true>
        <<<dim3(2, 1, NPLANE), 256, MM_SMEM>>>(
            pXH, pPCTW, pSPT, BC, LMAX, NLAT, NLAT, NLAT, LMAX,
            ROWS_BCK, LMAX * NLAT, BC * LMAX);

    // 3) transpose to coefficient order [bc][x]
    transpose_k<<<dim3((BC * LMAX) / 32, (NPLANE + 31) / 32), dim3(32, 8)>>>(
        pSPT, pSP, NPLANE, BC * LMAX);

    // 4) channel mix
    mix_k<<<NCOEF / 32, dim3(32, 4)>>>(pSP, wgt, pOUT);

    // 5) transpose back to plane-major [plane][bo][l]
    transpose_k<<<dim3((NPLANE + 31) / 32, (BC * LMAX) / 32), dim3(32, 8)>>>(
        pOUT, pOUTT, BC * LMAX, NPLANE);

    // 6) inverse Legendre: per plane, A=OUTT[plane](256x128), B=PCT_T[m](256x128)
    mmagemm<false, false, true>
        <<<dim3(2, 2, NPLANE), 256, MM_SMEM>>>(
            pOUTT, pPCT_T, pRR, BC, NLAT, LMAX, LMAX, LMAX, NLAT,
            BC * LMAX, NLAT * LMAX, ROWS_BCK);

    // 7) inverse DFT: A=RR plane-major (ATRANS), B=Gt[256][258] ld=260, C=y
    mmagemm<true, false, false>
        <<<dim3(ROWS_BCK / 128, 2, 1), 256, MM_SMEM>>>(
            pRR, pG, y, ROWS_BCK, NLON, NPLANE, ROWS_BCK, GLD, NLON, 0, 0, 0);
}